// round 1
// baseline (speedup 1.0000x reference)
#include <cuda_runtime.h>
#include <cuda_bf16.h>
#include <cstdint>

// Problem constants (fixed by reference)
#define BB 2
#define HH 64
#define WW 64
#define CC 192
#define NH 6
#define HD 32
#define KW 7
#define RR 13            // 2K-1
#define NPIX (BB*HH*WW)  // 8192

// Scratch (device globals: allocation-free)
__device__ float g_qkv[(size_t)NPIX * 3 * CC];  // [pixel][576] : q|k|v interleaved per pixel
__device__ float g_att[(size_t)NPIX * CC];      // attention output, c = head*32 + d

// ---------------------------------------------------------------------------
// GEMM: C[M,N] = A[M,Kd] * W[N,Kd]^T   (both row-major, NT)
// Tiles: BM=64, BN=64, BK=16; 256 threads; 4x4 per thread.
// mode==0: write to g_qkv, scale q-columns (col<192) by hd^-0.5 (A_in=x)
// mode==1: A = g_att, write to C_out (final projection)
// ---------------------------------------------------------------------------
#define BM 64
#define BN 64
#define BK 16

__global__ void gemm_nt_kernel(const float* __restrict__ A_in,
                               const float* __restrict__ W_in,
                               float* __restrict__ C_out,
                               int M, int N, int Kd, int mode)
{
    const float* A = (mode == 0) ? A_in : g_att;
    float*       Cp = (mode == 0) ? g_qkv : C_out;

    __shared__ float As[BK][BM];
    __shared__ float Bs[BK][BN];

    const int t  = threadIdx.x;
    const int tx = t & 15;        // 0..15 (N direction)
    const int ty = t >> 4;        // 0..15 (M direction)
    const int bm = blockIdx.y * BM;
    const int bn = blockIdx.x * BN;

    float acc[4][4] = {};

    const int lr = t >> 2;          // 0..63 : tile row to load
    const int lc = (t & 3) * 4;     // 0,4,8,12 : k offset

    for (int k0 = 0; k0 < Kd; k0 += BK) {
        float4 av = *(const float4*)(A    + (size_t)(bm + lr) * Kd + k0 + lc);
        float4 bv = *(const float4*)(W_in + (size_t)(bn + lr) * Kd + k0 + lc);
        As[lc + 0][lr] = av.x; As[lc + 1][lr] = av.y;
        As[lc + 2][lr] = av.z; As[lc + 3][lr] = av.w;
        Bs[lc + 0][lr] = bv.x; Bs[lc + 1][lr] = bv.y;
        Bs[lc + 2][lr] = bv.z; Bs[lc + 3][lr] = bv.w;
        __syncthreads();

        #pragma unroll
        for (int kk = 0; kk < BK; kk++) {
            float4 a4 = *(const float4*)&As[kk][ty * 4];
            float4 b4 = *(const float4*)&Bs[kk][tx * 4];
            float a[4] = {a4.x, a4.y, a4.z, a4.w};
            float b[4] = {b4.x, b4.y, b4.z, b4.w};
            #pragma unroll
            for (int u = 0; u < 4; u++)
                #pragma unroll
                for (int v = 0; v < 4; v++)
                    acc[u][v] += a[u] * b[v];
        }
        __syncthreads();
    }

    // q scale: entire 64-wide block column is uniformly q or not (192 % 64 == 0)
    const float qscale = 0.17677669529663687f; // 32^-0.5
    const bool scale_q = (mode == 0) && (bn < CC);

    #pragma unroll
    for (int u = 0; u < 4; u++) {
        float4 o;
        o.x = acc[u][0]; o.y = acc[u][1]; o.z = acc[u][2]; o.w = acc[u][3];
        if (scale_q) { o.x *= qscale; o.y *= qscale; o.z *= qscale; o.w *= qscale; }
        *(float4*)(Cp + (size_t)(bm + ty * 4 + u) * N + bn + tx * 4) = o;
    }
}

// ---------------------------------------------------------------------------
// Neighborhood attention: one warp per (pixel, head), lane = head-dim index.
// Single-pass online softmax (flash-style). k/v loads are 128B coalesced,
// served from L2 (each k/v row reused by up to 49 queries).
// ---------------------------------------------------------------------------
__global__ void natten_kernel(const float* __restrict__ rpb,
                              const float* __restrict__ temperature)
{
    __shared__ float s_rpb[NH * RR * RR];   // 1014 floats
    for (int idx = threadIdx.x; idx < NH * RR * RR; idx += blockDim.x)
        s_rpb[idx] = rpb[idx];
    __syncthreads();

    const int warp = threadIdx.x >> 5;
    const int lane = threadIdx.x & 31;
    const int task = blockIdx.x * (blockDim.x >> 5) + warp;   // 0 .. 49151
    const int n = task % NH;
    const int p = task / NH;                 // flat pixel
    const int j = p % WW;
    const int i = (p / WW) % HH;
    const int b = p / (HH * WW);

    const float qd = g_qkv[(size_t)p * (3 * CC) + n * HD + lane];  // pre-scaled
    const float tn = temperature[n];

    const int si = min(max(i - KW / 2, 0), HH - KW);
    const int sj = min(max(j - KW / 2, 0), WW - KW);

    const float* rpb_n = &s_rpb[n * RR * RR];
    const size_t bbase = (size_t)b * HH * WW;

    float m = -1e30f, l = 0.f, acc = 0.f;

    #pragma unroll
    for (int a = 0; a < KW; a++) {
        const int ii = si + a;
        const int ri = ii - i + (KW - 1);
        const float* rpb_row = rpb_n + ri * RR - j + (KW - 1);
        #pragma unroll
        for (int bb = 0; bb < KW; bb++) {
            const int jj = sj + bb;
            const size_t off = (bbase + (size_t)ii * WW + jj) * (3 * CC) + n * HD;
            // QK dot (warp reduce over 32 dims)
            float s = qd * g_qkv[off + CC + lane];
            s += __shfl_xor_sync(0xffffffffu, s, 16);
            s += __shfl_xor_sync(0xffffffffu, s, 8);
            s += __shfl_xor_sync(0xffffffffu, s, 4);
            s += __shfl_xor_sync(0xffffffffu, s, 2);
            s += __shfl_xor_sync(0xffffffffu, s, 1);
            s = (s + rpb_row[jj]) * tn;
            // online softmax + AV accumulation
            const float mn = fmaxf(m, s);
            const float corr = __expf(m - mn);
            const float e = __expf(s - mn);
            l = l * corr + e;
            acc = acc * corr + e * g_qkv[off + 2 * CC + lane];
            m = mn;
        }
    }

    g_att[(size_t)p * CC + n * HD + lane] = acc / l;
}

// ---------------------------------------------------------------------------
extern "C" void kernel_launch(void* const* d_in, const int* in_sizes, int n_in,
                              void* d_out, int out_size)
{
    const float* x      = (const float*)d_in[0];
    const float* w_qkv  = (const float*)d_in[1];
    const float* rpb    = (const float*)d_in[2];
    const float* temp   = (const float*)d_in[3];
    const float* w_proj = (const float*)d_in[4];
    float* out = (float*)d_out;

    // 1) QKV projection: [8192,192] x [576,192]^T -> g_qkv [8192,576], q scaled
    {
        dim3 grid(3 * CC / BN, NPIX / BM);   // (9, 128)
        gemm_nt_kernel<<<grid, 256>>>(x, w_qkv, nullptr, NPIX, 3 * CC, CC, 0);
    }

    // 2) neighborhood attention -> g_att [8192,192]
    {
        const int tasks = NPIX * NH;         // 49152
        const int threads = 256;             // 8 warps/block
        natten_kernel<<<tasks / 8, threads>>>(rpb, temp);
    }

    // 3) output projection: g_att [8192,192] x [192,192]^T -> out
    {
        dim3 grid(CC / BN, NPIX / BM);       // (3, 128)
        gemm_nt_kernel<<<grid, 256>>>(nullptr, w_proj, out, NPIX, CC, CC, 1);
    }
}

// round 2
// speedup vs baseline: 1.1575x; 1.1575x over previous
#include <cuda_runtime.h>
#include <cstdint>

#define BBATCH 2
#define HH 64
#define WW 64
#define CC 192
#define NH 6
#define HD 32
#define KW 7
#define RR 13
#define NPIX (BBATCH*HH*WW)

// scratch (device globals: allocation-free)
__device__ float g_qkv[(size_t)NPIX * 3 * CC];
__device__ float g_att[(size_t)NPIX * CC];

// ---------------------------------------------------------------------------
// GEMM: C[M,N] = A[M,Kd] * W[N,Kd]^T, row-major NT. 128 threads, TMxTN/thread.
// scaleQ: scale output cols < CC by hd^-0.5 (QKV pass).
// ---------------------------------------------------------------------------
template<int BM, int BN, int TM, int TN>
__global__ __launch_bounds__(128)
void gemm_nt(const float* __restrict__ A, const float* __restrict__ W,
             float* __restrict__ C, int N, int Kd, int scaleQ)
{
    constexpr int BK = 16;
    __shared__ float As[BK][BM];
    __shared__ float Bs[BK][BN];

    const int t  = threadIdx.x;
    const int bm = blockIdx.y * BM;
    const int bn = blockIdx.x * BN;
    constexpr int TCOLS = BN / TN;     // 8
    const int tx = t % TCOLS;
    const int ty = t / TCOLS;

    float acc[TM][TN] = {};

    for (int k0 = 0; k0 < Kd; k0 += BK) {
        // A tile: BM rows x 16 k, float4 chunks: f -> (row=f>>2, kc=f&3)
        #pragma unroll
        for (int f = t; f < BM * 4; f += 128) {
            const int row = f >> 2, kc = f & 3;
            float4 v = *(const float4*)(A + (size_t)(bm + row) * Kd + k0 + kc * 4);
            As[kc*4+0][row] = v.x; As[kc*4+1][row] = v.y;
            As[kc*4+2][row] = v.z; As[kc*4+3][row] = v.w;
        }
        #pragma unroll
        for (int f = t; f < BN * 4; f += 128) {
            const int row = f >> 2, kc = f & 3;
            float4 v = *(const float4*)(W + (size_t)(bn + row) * Kd + k0 + kc * 4);
            Bs[kc*4+0][row] = v.x; Bs[kc*4+1][row] = v.y;
            Bs[kc*4+2][row] = v.z; Bs[kc*4+3][row] = v.w;
        }
        __syncthreads();

        #pragma unroll
        for (int kk = 0; kk < BK; kk++) {
            float a[TM], b[TN];
            #pragma unroll
            for (int u = 0; u < TM; u += 4) {
                float4 v = *(const float4*)&As[kk][ty * TM + u];
                a[u] = v.x; a[u+1] = v.y; a[u+2] = v.z; a[u+3] = v.w;
            }
            #pragma unroll
            for (int v2 = 0; v2 < TN; v2 += 4) {
                float4 v = *(const float4*)&Bs[kk][tx * TN + v2];
                b[v2] = v.x; b[v2+1] = v.y; b[v2+2] = v.z; b[v2+3] = v.w;
            }
            #pragma unroll
            for (int u = 0; u < TM; u++)
                #pragma unroll
                for (int v2 = 0; v2 < TN; v2++)
                    acc[u][v2] += a[u] * b[v2];
        }
        __syncthreads();
    }

    const float qs = 0.17677669529663687f;   // 32^-0.5
    const bool doScale = scaleQ && (bn < CC);
    #pragma unroll
    for (int u = 0; u < TM; u++) {
        float* crow = C + (size_t)(bm + ty * TM + u) * N + bn + tx * TN;
        #pragma unroll
        for (int v2 = 0; v2 < TN; v2 += 4) {
            float4 o = make_float4(acc[u][v2], acc[u][v2+1], acc[u][v2+2], acc[u][v2+3]);
            if (doScale) { o.x *= qs; o.y *= qs; o.z *= qs; o.w *= qs; }
            *(float4*)(crow + v2) = o;
        }
    }
}

// ---------------------------------------------------------------------------
// Tiled neighborhood attention.
// Block: 4x32 pixel tile, one head, one batch. 128 threads = 1 thread/pixel.
// K/V neighborhood (10x38 rows x 32 dims) staged in smem, stride-33 rows
// (bank = (r + d) & 31; warp = one pixel row -> consecutive r -> conflict-free).
// Exact softmax over 49 register scores. q/output staged via smem for
// coalesced global traffic.
// ---------------------------------------------------------------------------
#define TILE_H 4
#define TILE_W 32
#define NRR (TILE_H + KW - 1)     // 10
#define NCC (TILE_W + KW - 1)     // 38
#define NNEI (NRR * NCC)          // 380
#define SROW 33
#define SM_FLOATS (2 * NNEI * SROW + RR * RR)

__global__ __launch_bounds__(128)
void natten2(const float* __restrict__ rpb, const float* __restrict__ temp)
{
    extern __shared__ float sm[];
    float* sK   = sm;
    float* sV   = sm + NNEI * SROW;
    float* srpb = sm + 2 * NNEI * SROW;

    const int t      = threadIdx.x;
    const int tile   = blockIdx.x;
    const int bI     = blockIdx.y;
    const int head   = blockIdx.z;
    const int tile_i = (tile >> 1) * TILE_H;
    const int tile_j = (tile & 1) * TILE_W;
    const int ti0 = min(max(tile_i - 3, 0), HH - NRR);
    const int tj0 = min(max(tile_j - 3, 0), WW - NCC);
    const int pixbase = bI * HH * WW;

    const float tn = temp[head];
    for (int idx = t; idx < RR * RR; idx += 128)
        srpb[idx] = rpb[head * RR * RR + idx] * tn;

    // stage q (coalesced gmem -> smem), then each thread grabs its row
    for (int idx = t; idx < 128 * HD; idx += 128) {
        const int d = idx & 31, lp = idx >> 5;
        const int gi = tile_i + (lp >> 5), gj = tile_j + (lp & 31);
        sK[lp * SROW + d] =
            g_qkv[(size_t)(pixbase + gi * WW + gj) * (3 * CC) + head * HD + d];
    }
    __syncthreads();
    float q[HD];
    #pragma unroll
    for (int d = 0; d < HD; d++) q[d] = sK[t * SROW + d] * tn;
    __syncthreads();

    // K, V neighborhood tiles
    for (int idx = t; idx < NNEI * HD; idx += 128) {
        const int d = idx & 31, r = idx >> 5;
        const int gi = ti0 + r / NCC, gj = tj0 + r % NCC;
        const size_t base =
            (size_t)(pixbase + gi * WW + gj) * (3 * CC) + CC + head * HD + d;
        sK[r * SROW + d] = g_qkv[base];
        sV[r * SROW + d] = g_qkv[base + CC];
    }
    __syncthreads();

    const int i  = tile_i + (t >> 5);
    const int j  = tile_j + (t & 31);
    const int si = min(max(i - 3, 0), HH - KW);
    const int sj = min(max(j - 3, 0), WW - KW);
    const int lr0 = si - ti0, lc0 = sj - tj0;
    const int ri0 = si - i + 6, rj0 = sj - j + 6;

    // scores init with (scaled) bias
    float s[49];
    #pragma unroll
    for (int a = 0; a < 7; a++)
        #pragma unroll
        for (int c = 0; c < 7; c++)
            s[a * 7 + c] = srpb[(ri0 + a) * RR + rj0 + c];

    // QK
    #pragma unroll
    for (int a = 0; a < 7; a++) {
        const float* kb = sK + ((lr0 + a) * NCC + lc0) * SROW;
        #pragma unroll
        for (int d = 0; d < HD; d++) {
            const float qd = q[d];
            #pragma unroll
            for (int c = 0; c < 7; c++)
                s[a * 7 + c] += qd * kb[c * SROW + d];
        }
    }

    // exact softmax
    float mx = s[0];
    #pragma unroll
    for (int n = 1; n < 49; n++) mx = fmaxf(mx, s[n]);
    float l = 0.f;
    #pragma unroll
    for (int n = 0; n < 49; n++) { s[n] = __expf(s[n] - mx); l += s[n]; }
    const float inv = 1.f / l;

    // AV
    float outv[HD];
    #pragma unroll
    for (int d = 0; d < HD; d++) outv[d] = 0.f;
    #pragma unroll
    for (int a = 0; a < 7; a++) {
        const float* vb = sV + ((lr0 + a) * NCC + lc0) * SROW;
        #pragma unroll
        for (int c = 0; c < 7; c++) {
            const float w = s[a * 7 + c];
            #pragma unroll
            for (int d = 0; d < HD; d++)
                outv[d] += w * vb[c * SROW + d];
        }
    }

    // stage output back through smem for coalesced store
    __syncthreads();
    #pragma unroll
    for (int d = 0; d < HD; d++) sK[t * SROW + d] = outv[d] * inv;
    __syncthreads();
    for (int idx = t; idx < 128 * HD; idx += 128) {
        const int d = idx & 31, lp = idx >> 5;
        const int gi = tile_i + (lp >> 5), gj = tile_j + (lp & 31);
        g_att[(size_t)(pixbase + gi * WW + gj) * CC + head * HD + d] =
            sK[lp * SROW + d];
    }
}

// ---------------------------------------------------------------------------
extern "C" void kernel_launch(void* const* d_in, const int* in_sizes, int n_in,
                              void* d_out, int out_size)
{
    const float* x      = (const float*)d_in[0];
    const float* w_qkv  = (const float*)d_in[1];
    const float* rpb    = (const float*)d_in[2];
    const float* temp   = (const float*)d_in[3];
    const float* w_proj = (const float*)d_in[4];
    float* out = (float*)d_out;

    void *qkvp, *attp;
    cudaGetSymbolAddress(&qkvp, g_qkv);
    cudaGetSymbolAddress(&attp, g_att);

    // 1) QKV projection: [8192,192] x [576,192]^T -> g_qkv (q pre-scaled)
    gemm_nt<128, 64, 8, 8><<<dim3(9, 64), 128>>>(x, w_qkv, (float*)qkvp,
                                                 3 * CC, CC, 1);

    // 2) tiled neighborhood attention -> g_att
    cudaFuncSetAttribute(natten2, cudaFuncAttributeMaxDynamicSharedMemorySize,
                         SM_FLOATS * 4);
    natten2<<<dim3(32, BBATCH, NH), 128, SM_FLOATS * 4>>>(rpb, temp);

    // 3) output projection: [8192,192] x [192,192]^T -> out
    gemm_nt<64, 64, 4, 8><<<dim3(3, 128), 128>>>((const float*)attp, w_proj,
                                                 out, CC, CC, 0);
}

// round 4
// speedup vs baseline: 2.3812x; 2.0572x over previous
#include <cuda_runtime.h>
#include <cstdint>

#define BBATCH 2
#define HH 64
#define WW 64
#define CC 192
#define NH 6
#define HD 32
#define KW 7
#define RR 13
#define NPIX (BBATCH*HH*WW)

// scratch (device globals: allocation-free)
__device__ float g_qkv[(size_t)NPIX * 3 * CC];
__device__ float g_att[(size_t)NPIX * CC];

__device__ __forceinline__ uint32_t f2tf32(float x) {
    uint32_t r;
    asm("cvt.rna.tf32.f32 %0, %1;" : "=r"(r) : "f"(x));   // sm_80+, no 'a' feature
    return r;
}

__device__ __forceinline__ void mma_tf32(float c[4], const uint32_t a[4],
                                         const uint32_t b[2]) {
    asm volatile(
        "mma.sync.aligned.m16n8k8.row.col.f32.tf32.tf32.f32 "
        "{%0,%1,%2,%3}, {%4,%5,%6,%7}, {%8,%9}, {%0,%1,%2,%3};"
        : "+f"(c[0]), "+f"(c[1]), "+f"(c[2]), "+f"(c[3])
        : "r"(a[0]), "r"(a[1]), "r"(a[2]), "r"(a[3]), "r"(b[0]), "r"(b[1]));
}

// ---------------------------------------------------------------------------
// Tensor-core GEMM via mma.sync tf32.
// C[M,N] = A[M,192] * W[N,192]^T, row-major NT.
// Block: 256 threads = 8 warps (4x2, M x N), tile 128x64, K-chunk 32.
// Each warp computes 32x32 = 2x4 mma tiles of m16n8k8.
// Smem tiles row-major, stride 36 words: fragment loads and staging stores
// are both bank-conflict-free.
// ---------------------------------------------------------------------------
#define GBM 128
#define GBN 64
#define GBK 32
#define GKD 192
#define GST 36

__global__ __launch_bounds__(256)
void gemm_mma(const float* __restrict__ A, const float* __restrict__ W,
              float* __restrict__ C, int Ncols, int scaleQ)
{
    __shared__ uint32_t As[GBM][GST];
    __shared__ uint32_t Bs[GBN][GST];

    const int t    = threadIdx.x;
    const int wid  = t >> 5, lane = t & 31;
    const int g    = lane >> 2, q4 = lane & 3;
    const int wM   = wid >> 1, wN = wid & 1;
    const int bm   = blockIdx.y * GBM;
    const int bn   = blockIdx.x * GBN;

    float acc[2][4][4] = {};

    for (int kc = 0; kc < GKD; kc += GBK) {
        // stage A tile: 128 rows x 32 k (8 float4/row)
        #pragma unroll
        for (int f = t; f < GBM * 8; f += 256) {
            const int row = f >> 3, c4 = f & 7;
            const float4 v = *(const float4*)(A + (size_t)(bm + row) * GKD + kc + c4 * 4);
            *(uint4*)&As[row][c4 * 4] =
                make_uint4(f2tf32(v.x), f2tf32(v.y), f2tf32(v.z), f2tf32(v.w));
        }
        // stage B (weight) tile: 64 rows x 32 k
        #pragma unroll
        for (int f = t; f < GBN * 8; f += 256) {
            const int row = f >> 3, c4 = f & 7;
            const float4 v = *(const float4*)(W + (size_t)(bn + row) * GKD + kc + c4 * 4);
            *(uint4*)&Bs[row][c4 * 4] =
                make_uint4(f2tf32(v.x), f2tf32(v.y), f2tf32(v.z), f2tf32(v.w));
        }
        __syncthreads();

        #pragma unroll
        for (int k8 = 0; k8 < GBK / 8; k8++) {
            uint32_t a[2][4], b[4][2];
            #pragma unroll
            for (int mt = 0; mt < 2; mt++) {
                const uint32_t* ap = &As[wM * 32 + mt * 16 + g][k8 * 8 + q4];
                a[mt][0] = ap[0];
                a[mt][1] = ap[8 * GST];
                a[mt][2] = ap[4];
                a[mt][3] = ap[8 * GST + 4];
            }
            #pragma unroll
            for (int nt = 0; nt < 4; nt++) {
                const uint32_t* bp = &Bs[wN * 32 + nt * 8 + g][k8 * 8 + q4];
                b[nt][0] = bp[0];
                b[nt][1] = bp[4];
            }
            #pragma unroll
            for (int mt = 0; mt < 2; mt++)
                #pragma unroll
                for (int nt = 0; nt < 4; nt++)
                    mma_tf32(acc[mt][nt], a[mt], b[nt]);
        }
        __syncthreads();
    }

    // epilogue
    const float sc = (scaleQ && bn < CC) ? 0.17677669529663687f : 1.0f;
    #pragma unroll
    for (int mt = 0; mt < 2; mt++) {
        const int row0 = bm + wM * 32 + mt * 16 + g;
        #pragma unroll
        for (int nt = 0; nt < 4; nt++) {
            const int col = bn + wN * 32 + nt * 8 + q4 * 2;
            float2 lo = make_float2(acc[mt][nt][0] * sc, acc[mt][nt][1] * sc);
            float2 hi = make_float2(acc[mt][nt][2] * sc, acc[mt][nt][3] * sc);
            *(float2*)(C + (size_t)row0 * Ncols + col) = lo;
            *(float2*)(C + (size_t)(row0 + 8) * Ncols + col) = hi;
        }
    }
}

// ---------------------------------------------------------------------------
// Tiled neighborhood attention (float4-vectorized smem).
// Block: 4x32 pixel tile, one head, one batch; 128 threads = 1 thread/pixel.
// K/V neighborhood (10x38 rows x 32 dims) in smem with 36-float row stride
// (16B aligned rows; LDS.128 per-phase banks 4*lane -> conflict-free).
// ---------------------------------------------------------------------------
#define TILE_H 4
#define TILE_W 32
#define NRR (TILE_H + KW - 1)     // 10
#define NCC (TILE_W + KW - 1)     // 38
#define NNEI (NRR * NCC)          // 380
#define SROW 36
#define SM_FLOATS (2 * NNEI * SROW + RR * RR)

__global__ __launch_bounds__(128)
void natten2(const float* __restrict__ rpb, const float* __restrict__ temp)
{
    extern __shared__ float sm[];
    float* sK   = sm;
    float* sV   = sm + NNEI * SROW;
    float* srpb = sm + 2 * NNEI * SROW;

    const int t      = threadIdx.x;
    const int tile   = blockIdx.x;
    const int bI     = blockIdx.y;
    const int head   = blockIdx.z;
    const int tile_i = (tile >> 1) * TILE_H;
    const int tile_j = (tile & 1) * TILE_W;
    const int ti0 = min(max(tile_i - 3, 0), HH - NRR);
    const int tj0 = min(max(tile_j - 3, 0), WW - NCC);
    const int pixbase = bI * HH * WW;

    const float tn = temp[head];
    for (int idx = t; idx < RR * RR; idx += 128)
        srpb[idx] = rpb[head * RR * RR + idx] * tn;

    // K, V neighborhood tiles: float4 granularity
    for (int idx = t; idx < NNEI * 8; idx += 128) {
        const int d4 = idx & 7, r = idx >> 3;
        const int gi = ti0 + r / NCC, gj = tj0 + r % NCC;
        const float* base =
            g_qkv + (size_t)(pixbase + gi * WW + gj) * (3 * CC) + CC + head * HD;
        *(float4*)(sK + r * SROW + d4 * 4) = *(const float4*)(base + d4 * 4);
        *(float4*)(sV + r * SROW + d4 * 4) = *(const float4*)(base + CC + d4 * 4);
    }

    // q: per-thread direct load (pre-scaled by qscale in GEMM; apply temperature)
    const int i  = tile_i + (t >> 5);
    const int j  = tile_j + (t & 31);
    const int pix = pixbase + i * WW + j;
    float4 q4[8];
    {
        const float4* qp = (const float4*)(g_qkv + (size_t)pix * (3 * CC) + head * HD);
        #pragma unroll
        for (int d4 = 0; d4 < 8; d4++) {
            float4 v = qp[d4];
            v.x *= tn; v.y *= tn; v.z *= tn; v.w *= tn;
            q4[d4] = v;
        }
    }
    __syncthreads();

    const int si = min(max(i - 3, 0), HH - KW);
    const int sj = min(max(j - 3, 0), WW - KW);
    const int lr0 = si - ti0, lc0 = sj - tj0;
    const int ri0 = si - i + 6, rj0 = sj - j + 6;

    // scores init with temperature-scaled bias
    float s[49];
    #pragma unroll
    for (int a = 0; a < 7; a++)
        #pragma unroll
        for (int c = 0; c < 7; c++)
            s[a * 7 + c] = srpb[(ri0 + a) * RR + rj0 + c];

    // QK (vectorized LDS.128)
    #pragma unroll
    for (int a = 0; a < 7; a++) {
        const float4* kb = (const float4*)(sK + ((lr0 + a) * NCC + lc0) * SROW);
        #pragma unroll
        for (int c = 0; c < 7; c++) {
            const float4* kr = kb + c * (SROW / 4);
            float acc = s[a * 7 + c];
            #pragma unroll
            for (int d4 = 0; d4 < 8; d4++) {
                const float4 kv = kr[d4];
                acc += q4[d4].x * kv.x + q4[d4].y * kv.y
                     + q4[d4].z * kv.z + q4[d4].w * kv.w;
            }
            s[a * 7 + c] = acc;
        }
    }

    // exact softmax
    float mx = s[0];
    #pragma unroll
    for (int n = 1; n < 49; n++) mx = fmaxf(mx, s[n]);
    float l = 0.f;
    #pragma unroll
    for (int n = 0; n < 49; n++) { s[n] = __expf(s[n] - mx); l += s[n]; }
    const float inv = 1.f / l;

    // AV
    float4 o4[8];
    #pragma unroll
    for (int d4 = 0; d4 < 8; d4++) o4[d4] = make_float4(0.f, 0.f, 0.f, 0.f);
    #pragma unroll
    for (int a = 0; a < 7; a++) {
        const float4* vb = (const float4*)(sV + ((lr0 + a) * NCC + lc0) * SROW);
        #pragma unroll
        for (int c = 0; c < 7; c++) {
            const float4* vr = vb + c * (SROW / 4);
            const float w = s[a * 7 + c];
            #pragma unroll
            for (int d4 = 0; d4 < 8; d4++) {
                const float4 vv = vr[d4];
                o4[d4].x += w * vv.x; o4[d4].y += w * vv.y;
                o4[d4].z += w * vv.z; o4[d4].w += w * vv.w;
            }
        }
    }

    float4* op = (float4*)(g_att + (size_t)pix * CC + head * HD);
    #pragma unroll
    for (int d4 = 0; d4 < 8; d4++) {
        float4 o = o4[d4];
        o.x *= inv; o.y *= inv; o.z *= inv; o.w *= inv;
        op[d4] = o;
    }
}

// ---------------------------------------------------------------------------
extern "C" void kernel_launch(void* const* d_in, const int* in_sizes, int n_in,
                              void* d_out, int out_size)
{
    const float* x      = (const float*)d_in[0];
    const float* w_qkv  = (const float*)d_in[1];
    const float* rpb    = (const float*)d_in[2];
    const float* temp   = (const float*)d_in[3];
    const float* w_proj = (const float*)d_in[4];
    float* out = (float*)d_out;

    void *qkvp, *attp;
    cudaGetSymbolAddress(&qkvp, g_qkv);
    cudaGetSymbolAddress(&attp, g_att);

    cudaFuncSetAttribute(natten2, cudaFuncAttributeMaxDynamicSharedMemorySize,
                         SM_FLOATS * 4);

    // 1) QKV projection: [8192,192] x [576,192]^T -> g_qkv (q pre-scaled)
    gemm_mma<<<dim3(9, NPIX / GBM), 256>>>(x, w_qkv, (float*)qkvp, 3 * CC, 1);

    // 2) tiled neighborhood attention -> g_att
    natten2<<<dim3(32, BBATCH, NH), 128, SM_FLOATS * 4>>>(rpb, temp);

    // 3) output projection: [8192,192] x [192,192]^T -> out
    gemm_mma<<<dim3(3, NPIX / GBM), 256>>>((const float*)attp, w_proj, out, CC, 0);
}

// round 5
// speedup vs baseline: 2.5221x; 1.0591x over previous
#include <cuda_runtime.h>
#include <cstdint>

#define BBATCH 2
#define HH 64
#define WW 64
#define CC 192
#define NH 6
#define HD 32
#define KW 7
#define RR 13
#define NPIX (BBATCH*HH*WW)

// scratch (device globals: allocation-free)
__device__ float g_qkv[(size_t)NPIX * 3 * CC];
__device__ float g_att[(size_t)NPIX * CC];

__device__ __forceinline__ uint32_t f2tf32(float x) {
    uint32_t r;
    asm("cvt.rna.tf32.f32 %0, %1;" : "=r"(r) : "f"(x));   // sm_80+, no 'a' feature
    return r;
}
__device__ __forceinline__ uint4 cvt4(float4 v) {
    return make_uint4(f2tf32(v.x), f2tf32(v.y), f2tf32(v.z), f2tf32(v.w));
}

__device__ __forceinline__ void mma_tf32(float c[4], const uint32_t a[4],
                                         const uint32_t b[2]) {
    asm volatile(
        "mma.sync.aligned.m16n8k8.row.col.f32.tf32.tf32.f32 "
        "{%0,%1,%2,%3}, {%4,%5,%6,%7}, {%8,%9}, {%0,%1,%2,%3};"
        : "+f"(c[0]), "+f"(c[1]), "+f"(c[2]), "+f"(c[3])
        : "r"(a[0]), "r"(a[1]), "r"(a[2]), "r"(a[3]), "r"(b[0]), "r"(b[1]));
}

// ---------------------------------------------------------------------------
// Tensor-core GEMM via mma.sync tf32, software-pipelined, double-buffered.
// C[M,N] = A[M,192] * W[N,192]^T, row-major NT.
// Block: 256 threads = 8 warps (4x2 M x N), tile 128x64, K-chunk 32.
// Each warp computes 32x32 = 2x4 mma tiles of m16n8k8.
// Loop: STS(buf) -> sync -> LDG(next chunk -> regs) -> MMA(buf).
// ---------------------------------------------------------------------------
#define GBM 128
#define GBN 64
#define GBK 32
#define GKD 192
#define NCHUNK (GKD / GBK)      // 6
#define GST 36

__global__ __launch_bounds__(256)
void gemm_mma(const float* __restrict__ A, const float* __restrict__ W,
              float* __restrict__ C, int Ncols, int scaleQ)
{
    __shared__ uint32_t As[2][GBM][GST];
    __shared__ uint32_t Bs[2][GBN][GST];

    const int t    = threadIdx.x;
    const int wid  = t >> 5, lane = t & 31;
    const int g    = lane >> 2, q4 = lane & 3;
    const int wM   = wid >> 1, wN = wid & 1;
    const int bm   = blockIdx.y * GBM;
    const int bn   = blockIdx.x * GBN;

    // per-thread staging slots: A -> 4 float4, B -> 2 float4
    int arow[4], ac4[4], brow[2], bc4[2];
    #pragma unroll
    for (int i = 0; i < 4; i++) {
        const int f = t + i * 256;
        arow[i] = f >> 3; ac4[i] = f & 7;
    }
    #pragma unroll
    for (int i = 0; i < 2; i++) {
        const int f = t + i * 256;
        brow[i] = f >> 3; bc4[i] = f & 7;
    }

    float4 ra[4], rb[2];
    #pragma unroll
    for (int i = 0; i < 4; i++)
        ra[i] = *(const float4*)(A + (size_t)(bm + arow[i]) * GKD + ac4[i] * 4);
    #pragma unroll
    for (int i = 0; i < 2; i++)
        rb[i] = *(const float4*)(W + (size_t)(bn + brow[i]) * GKD + bc4[i] * 4);

    float acc[2][4][4] = {};

    #pragma unroll
    for (int kc = 0; kc < NCHUNK; kc++) {
        const int buf = kc & 1;
        #pragma unroll
        for (int i = 0; i < 4; i++)
            *(uint4*)&As[buf][arow[i]][ac4[i] * 4] = cvt4(ra[i]);
        #pragma unroll
        for (int i = 0; i < 2; i++)
            *(uint4*)&Bs[buf][brow[i]][bc4[i] * 4] = cvt4(rb[i]);
        __syncthreads();

        if (kc + 1 < NCHUNK) {
            const int ko = (kc + 1) * GBK;
            #pragma unroll
            for (int i = 0; i < 4; i++)
                ra[i] = *(const float4*)(A + (size_t)(bm + arow[i]) * GKD + ko + ac4[i] * 4);
            #pragma unroll
            for (int i = 0; i < 2; i++)
                rb[i] = *(const float4*)(W + (size_t)(bn + brow[i]) * GKD + ko + bc4[i] * 4);
        }

        #pragma unroll
        for (int k8 = 0; k8 < GBK / 8; k8++) {
            uint32_t a[2][4], b[4][2];
            #pragma unroll
            for (int mt = 0; mt < 2; mt++) {
                const uint32_t* ap = &As[buf][wM * 32 + mt * 16 + g][k8 * 8 + q4];
                a[mt][0] = ap[0];
                a[mt][1] = ap[8 * GST];
                a[mt][2] = ap[4];
                a[mt][3] = ap[8 * GST + 4];
            }
            #pragma unroll
            for (int nt = 0; nt < 4; nt++) {
                const uint32_t* bp = &Bs[buf][wN * 32 + nt * 8 + g][k8 * 8 + q4];
                b[nt][0] = bp[0];
                b[nt][1] = bp[4];
            }
            #pragma unroll
            for (int mt = 0; mt < 2; mt++)
                #pragma unroll
                for (int nt = 0; nt < 4; nt++)
                    mma_tf32(acc[mt][nt], a[mt], b[nt]);
        }
        __syncthreads();
    }

    // epilogue
    const float sc = (scaleQ && bn < CC) ? 0.17677669529663687f : 1.0f;
    #pragma unroll
    for (int mt = 0; mt < 2; mt++) {
        const int row0 = bm + wM * 32 + mt * 16 + g;
        #pragma unroll
        for (int nt = 0; nt < 4; nt++) {
            const int col = bn + wN * 32 + nt * 8 + q4 * 2;
            float2 lo = make_float2(acc[mt][nt][0] * sc, acc[mt][nt][1] * sc);
            float2 hi = make_float2(acc[mt][nt][2] * sc, acc[mt][nt][3] * sc);
            *(float2*)(C + (size_t)row0 * Ncols + col) = lo;
            *(float2*)(C + (size_t)(row0 + 8) * Ncols + col) = hi;
        }
    }
}

// ---------------------------------------------------------------------------
// Tiled neighborhood attention (float4-vectorized smem).
// Block: 4x32 pixel tile, one head, one batch; 128 threads = 1 thread/pixel.
// K/V neighborhood (10x38 rows x 32 dims) in smem with 36-float row stride.
// ---------------------------------------------------------------------------
#define TILE_H 4
#define TILE_W 32
#define NRR (TILE_H + KW - 1)     // 10
#define NCC (TILE_W + KW - 1)     // 38
#define NNEI (NRR * NCC)          // 380
#define SROW 36
#define SM_FLOATS (2 * NNEI * SROW + RR * RR)

__global__ __launch_bounds__(128)
void natten2(const float* __restrict__ rpb, const float* __restrict__ temp)
{
    extern __shared__ float sm[];
    float* sK   = sm;
    float* sV   = sm + NNEI * SROW;
    float* srpb = sm + 2 * NNEI * SROW;

    const int t      = threadIdx.x;
    const int tile   = blockIdx.x;
    const int bI     = blockIdx.y;
    const int head   = blockIdx.z;
    const int tile_i = (tile >> 1) * TILE_H;
    const int tile_j = (tile & 1) * TILE_W;
    const int ti0 = min(max(tile_i - 3, 0), HH - NRR);
    const int tj0 = min(max(tile_j - 3, 0), WW - NCC);
    const int pixbase = bI * HH * WW;

    const float tn = temp[head];
    for (int idx = t; idx < RR * RR; idx += 128)
        srpb[idx] = rpb[head * RR * RR + idx] * tn;

    // K, V neighborhood tiles: float4 granularity
    for (int idx = t; idx < NNEI * 8; idx += 128) {
        const int d4 = idx & 7, r = idx >> 3;
        const int gi = ti0 + r / NCC, gj = tj0 + r % NCC;
        const float* base =
            g_qkv + (size_t)(pixbase + gi * WW + gj) * (3 * CC) + CC + head * HD;
        *(float4*)(sK + r * SROW + d4 * 4) = *(const float4*)(base + d4 * 4);
        *(float4*)(sV + r * SROW + d4 * 4) = *(const float4*)(base + CC + d4 * 4);
    }

    const int i  = tile_i + (t >> 5);
    const int j  = tile_j + (t & 31);
    const int pix = pixbase + i * WW + j;
    float4 q4[8];
    {
        const float4* qp = (const float4*)(g_qkv + (size_t)pix * (3 * CC) + head * HD);
        #pragma unroll
        for (int d4 = 0; d4 < 8; d4++) {
            float4 v = qp[d4];
            v.x *= tn; v.y *= tn; v.z *= tn; v.w *= tn;
            q4[d4] = v;
        }
    }
    __syncthreads();

    const int si = min(max(i - 3, 0), HH - KW);
    const int sj = min(max(j - 3, 0), WW - KW);
    const int lr0 = si - ti0, lc0 = sj - tj0;
    const int ri0 = si - i + 6, rj0 = sj - j + 6;

    float s[49];
    #pragma unroll
    for (int a = 0; a < 7; a++)
        #pragma unroll
        for (int c = 0; c < 7; c++)
            s[a * 7 + c] = srpb[(ri0 + a) * RR + rj0 + c];

    // QK (vectorized LDS.128)
    #pragma unroll
    for (int a = 0; a < 7; a++) {
        const float4* kb = (const float4*)(sK + ((lr0 + a) * NCC + lc0) * SROW);
        #pragma unroll
        for (int c = 0; c < 7; c++) {
            const float4* kr = kb + c * (SROW / 4);
            float acc = s[a * 7 + c];
            #pragma unroll
            for (int d4 = 0; d4 < 8; d4++) {
                const float4 kv = kr[d4];
                acc += q4[d4].x * kv.x + q4[d4].y * kv.y
                     + q4[d4].z * kv.z + q4[d4].w * kv.w;
            }
            s[a * 7 + c] = acc;
        }
    }

    float mx = s[0];
    #pragma unroll
    for (int n = 1; n < 49; n++) mx = fmaxf(mx, s[n]);
    float l = 0.f;
    #pragma unroll
    for (int n = 0; n < 49; n++) { s[n] = __expf(s[n] - mx); l += s[n]; }
    const float inv = 1.f / l;

    float4 o4[8];
    #pragma unroll
    for (int d4 = 0; d4 < 8; d4++) o4[d4] = make_float4(0.f, 0.f, 0.f, 0.f);
    #pragma unroll
    for (int a = 0; a < 7; a++) {
        const float4* vb = (const float4*)(sV + ((lr0 + a) * NCC + lc0) * SROW);
        #pragma unroll
        for (int c = 0; c < 7; c++) {
            const float4* vr = vb + c * (SROW / 4);
            const float w = s[a * 7 + c];
            #pragma unroll
            for (int d4 = 0; d4 < 8; d4++) {
                const float4 vv = vr[d4];
                o4[d4].x += w * vv.x; o4[d4].y += w * vv.y;
                o4[d4].z += w * vv.z; o4[d4].w += w * vv.w;
            }
        }
    }

    float4* op = (float4*)(g_att + (size_t)pix * CC + head * HD);
    #pragma unroll
    for (int d4 = 0; d4 < 8; d4++) {
        float4 o = o4[d4];
        o.x *= inv; o.y *= inv; o.z *= inv; o.w *= inv;
        op[d4] = o;
    }
}

// ---------------------------------------------------------------------------
extern "C" void kernel_launch(void* const* d_in, const int* in_sizes, int n_in,
                              void* d_out, int out_size)
{
    const float* x      = (const float*)d_in[0];
    const float* w_qkv  = (const float*)d_in[1];
    const float* rpb    = (const float*)d_in[2];
    const float* temp   = (const float*)d_in[3];
    const float* w_proj = (const float*)d_in[4];
    float* out = (float*)d_out;

    void *qkvp, *attp;
    cudaGetSymbolAddress(&qkvp, g_qkv);
    cudaGetSymbolAddress(&attp, g_att);

    cudaFuncSetAttribute(natten2, cudaFuncAttributeMaxDynamicSharedMemorySize,
                         SM_FLOATS * 4);

    // 1) QKV projection: [8192,192] x [576,192]^T -> g_qkv (q pre-scaled)
    gemm_mma<<<dim3(9, NPIX / GBM), 256>>>(x, w_qkv, (float*)qkvp, 3 * CC, 1);

    // 2) tiled neighborhood attention -> g_att
    natten2<<<dim3(32, BBATCH, NH), 128, SM_FLOATS * 4>>>(rpb, temp);

    // 3) output projection: [8192,192] x [192,192]^T -> out
    gemm_mma<<<dim3(3, NPIX / GBM), 256>>>((const float*)attp, w_proj, out, CC, 0);
}

// round 6
// speedup vs baseline: 2.7355x; 1.0846x over previous
#include <cuda_runtime.h>
#include <cstdint>

#define BBATCH 2
#define HH 64
#define WW 64
#define CC 192
#define NH 6
#define HD 32
#define KW 7
#define RR 13
#define NPIX (BBATCH*HH*WW)

// scratch (device globals: allocation-free)
__device__ float g_qkv[(size_t)NPIX * 3 * CC];   // qkv activations (tf32-rounded q? no: raw fp32 outputs)
__device__ float g_att[(size_t)NPIX * CC];       // attention output (tf32-rounded at write)
__device__ float g_xr [(size_t)NPIX * CC];       // x, tf32-rounded
__device__ float g_wqr[(size_t)3 * CC * CC];     // w_qkv, tf32-rounded
__device__ float g_wpr[(size_t)CC * CC];         // w_proj, tf32-rounded

__device__ __forceinline__ uint32_t f2tf32(float x) {
    uint32_t r;
    asm("cvt.rna.tf32.f32 %0, %1;" : "=r"(r) : "f"(x));   // sm_80+, no 'a' feature
    return r;
}

__device__ __forceinline__ uint32_t smem_u32(const void* p) {
    uint32_t a;
    asm("{ .reg .u64 t; cvta.to.shared.u64 t, %1; cvt.u32.u64 %0, t; }"
        : "=r"(a) : "l"(p));
    return a;
}

__device__ __forceinline__ void cp16(uint32_t dst, const void* src) {
    asm volatile("cp.async.cg.shared.global [%0], [%1], 16;"
                 :: "r"(dst), "l"(src));
}
#define CP_COMMIT() asm volatile("cp.async.commit_group;" ::: "memory")
#define CP_WAIT(N)  asm volatile("cp.async.wait_group %0;" :: "n"(N) : "memory")

__device__ __forceinline__ void mma_tf32(float c[4], const uint32_t a[4],
                                         const uint32_t b[2]) {
    asm volatile(
        "mma.sync.aligned.m16n8k8.row.col.f32.tf32.tf32.f32 "
        "{%0,%1,%2,%3}, {%4,%5,%6,%7}, {%8,%9}, {%0,%1,%2,%3};"
        : "+f"(c[0]), "+f"(c[1]), "+f"(c[2]), "+f"(c[3])
        : "r"(a[0]), "r"(a[1]), "r"(a[2]), "r"(a[3]), "r"(b[0]), "r"(b[1]));
}

// ---------------------------------------------------------------------------
// Pre-pass: round three fp32 arrays to tf32-representable fp32.
// ---------------------------------------------------------------------------
#define N4X ((NPIX * CC) / 4)          // 393216
#define N4Q ((3 * CC * CC) / 4)        // 27648
#define N4P ((CC * CC) / 4)            // 9216
#define N4TOT (N4X + N4Q + N4P)        // 430080

__global__ __launch_bounds__(256)
void round_pass(const float* __restrict__ x, const float* __restrict__ wq,
                const float* __restrict__ wp)
{
    const int idx = blockIdx.x * 256 + threadIdx.x;
    if (idx >= N4TOT) return;
    const float4* src;
    float4* dst;
    int off;
    if (idx < N4X)            { src = (const float4*)x;  dst = (float4*)g_xr;  off = idx; }
    else if (idx < N4X + N4Q) { src = (const float4*)wq; dst = (float4*)g_wqr; off = idx - N4X; }
    else                      { src = (const float4*)wp; dst = (float4*)g_wpr; off = idx - N4X - N4Q; }
    const float4 v = src[off];
    float4 o;
    o.x = __uint_as_float(f2tf32(v.x));
    o.y = __uint_as_float(f2tf32(v.y));
    o.z = __uint_as_float(f2tf32(v.z));
    o.w = __uint_as_float(f2tf32(v.w));
    dst[off] = o;
}

// ---------------------------------------------------------------------------
// Tensor-core GEMM via mma.sync tf32, cp.async double-buffered pipeline.
// C[M,N] = A[M,192] * W[N,192]^T, row-major NT, inputs pre-rounded to tf32.
// Block 256 threads = 8 warps (4x2 M x N), tile 128x64, K-chunk 32.
// Smem: unpadded 128B rows with XOR-16B swizzle (c16 ^= r&7) — staging and
// fragment LDS both bank-conflict-free. 48KB static -> 4 CTAs/SM.
// ---------------------------------------------------------------------------
#define GBM 128
#define GBN 64
#define GBK 32
#define GKD 192
#define NCHUNK (GKD / GBK)      // 6

__global__ __launch_bounds__(256)
void gemm_mma(const float* __restrict__ A, const float* __restrict__ W,
              float* __restrict__ C, int Ncols, int scaleQ)
{
    __shared__ uint32_t As[2][GBM][GBK];   // 32 KB
    __shared__ uint32_t Bs[2][GBN][GBK];   // 16 KB

    const int t    = threadIdx.x;
    const int wid  = t >> 5, lane = t & 31;
    const int g    = lane >> 2, q4 = lane & 3;
    const int wM   = wid >> 1, wN = wid & 1;
    const int bm   = blockIdx.y * GBM;
    const int bn   = blockIdx.x * GBN;

    // staging assignments: A 4 units/thread, B 2 units/thread (16B units)
    // unit u of A: r = u>>3, c16 = u&7 ; swizzled dst col16 = c16 ^ (r&7)
    uint32_t a_dst[2][4], b_dst[2][2];
    const float* a_src[4];
    const float* b_src[2];
    #pragma unroll
    for (int i = 0; i < 4; i++) {
        const int u = t + i * 256, r = u >> 3, c = u & 7;
        a_src[i] = A + (size_t)(bm + r) * GKD + c * 4;
        #pragma unroll
        for (int bf = 0; bf < 2; bf++)
            a_dst[bf][i] = smem_u32(&As[bf][r][(c ^ (r & 7)) * 4]);
    }
    #pragma unroll
    for (int i = 0; i < 2; i++) {
        const int u = t + i * 256, r = u >> 3, c = u & 7;
        b_src[i] = W + (size_t)(bn + r) * GKD + c * 4;
        #pragma unroll
        for (int bf = 0; bf < 2; bf++)
            b_dst[bf][i] = smem_u32(&Bs[bf][r][(c ^ (r & 7)) * 4]);
    }

    // prefetch chunk 0 -> buf 0
    #pragma unroll
    for (int i = 0; i < 4; i++) cp16(a_dst[0][i], a_src[i]);
    #pragma unroll
    for (int i = 0; i < 2; i++) cp16(b_dst[0][i], b_src[i]);
    CP_COMMIT();

    float acc[2][4][4] = {};

    #pragma unroll
    for (int kc = 0; kc < NCHUNK; kc++) {
        const int buf = kc & 1;
        if (kc + 1 < NCHUNK) {
            const int ko = (kc + 1) * GBK;
            const int nb = (kc + 1) & 1;
            #pragma unroll
            for (int i = 0; i < 4; i++) cp16(a_dst[nb][i], a_src[i] + ko);
            #pragma unroll
            for (int i = 0; i < 2; i++) cp16(b_dst[nb][i], b_src[i] + ko);
            CP_COMMIT();
            CP_WAIT(1);
        } else {
            CP_WAIT(0);
        }
        __syncthreads();

        #pragma unroll
        for (int k8 = 0; k8 < GBK / 8; k8++) {
            // swizzled word cols for this (k8, g, q4)
            const int w0 = ((k8 * 2) ^ g) * 4 + q4;
            const int w1 = ((k8 * 2 + 1) ^ g) * 4 + q4;
            uint32_t a[2][4], b[4][2];
            #pragma unroll
            for (int mt = 0; mt < 2; mt++) {
                const int r = wM * 32 + mt * 16 + g;
                a[mt][0] = As[buf][r][w0];
                a[mt][1] = As[buf][r + 8][w0];
                a[mt][2] = As[buf][r][w1];
                a[mt][3] = As[buf][r + 8][w1];
            }
            #pragma unroll
            for (int nt = 0; nt < 4; nt++) {
                const int r = wN * 32 + nt * 8 + g;
                b[nt][0] = Bs[buf][r][w0];
                b[nt][1] = Bs[buf][r][w1];
            }
            #pragma unroll
            for (int mt = 0; mt < 2; mt++)
                #pragma unroll
                for (int nt = 0; nt < 4; nt++)
                    mma_tf32(acc[mt][nt], a[mt], b[nt]);
        }
        __syncthreads();
    }

    // epilogue
    const float sc = (scaleQ && bn < CC) ? 0.17677669529663687f : 1.0f;
    #pragma unroll
    for (int mt = 0; mt < 2; mt++) {
        const int row0 = bm + wM * 32 + mt * 16 + g;
        #pragma unroll
        for (int nt = 0; nt < 4; nt++) {
            const int col = bn + wN * 32 + nt * 8 + q4 * 2;
            float2 lo = make_float2(acc[mt][nt][0] * sc, acc[mt][nt][1] * sc);
            float2 hi = make_float2(acc[mt][nt][2] * sc, acc[mt][nt][3] * sc);
            *(float2*)(C + (size_t)row0 * Ncols + col) = lo;
            *(float2*)(C + (size_t)(row0 + 8) * Ncols + col) = hi;
        }
    }
}

// ---------------------------------------------------------------------------
// Tiled neighborhood attention (float4-vectorized smem).
// Block: 4x32 pixel tile, one head, one batch; 128 threads = 1 thread/pixel.
// Output written tf32-rounded (feeds proj GEMM directly).
// ---------------------------------------------------------------------------
#define TILE_H 4
#define TILE_W 32
#define NRR (TILE_H + KW - 1)     // 10
#define NCC (TILE_W + KW - 1)     // 38
#define NNEI (NRR * NCC)          // 380
#define SROW 36
#define SM_FLOATS (2 * NNEI * SROW + RR * RR)

__global__ __launch_bounds__(128)
void natten2(const float* __restrict__ rpb, const float* __restrict__ temp)
{
    extern __shared__ float sm[];
    float* sK   = sm;
    float* sV   = sm + NNEI * SROW;
    float* srpb = sm + 2 * NNEI * SROW;

    const int t      = threadIdx.x;
    const int tile   = blockIdx.x;
    const int bI     = blockIdx.y;
    const int head   = blockIdx.z;
    const int tile_i = (tile >> 1) * TILE_H;
    const int tile_j = (tile & 1) * TILE_W;
    const int ti0 = min(max(tile_i - 3, 0), HH - NRR);
    const int tj0 = min(max(tile_j - 3, 0), WW - NCC);
    const int pixbase = bI * HH * WW;

    const float tn = temp[head];
    for (int idx = t; idx < RR * RR; idx += 128)
        srpb[idx] = rpb[head * RR * RR + idx] * tn;

    for (int idx = t; idx < NNEI * 8; idx += 128) {
        const int d4 = idx & 7, r = idx >> 3;
        const int gi = ti0 + r / NCC, gj = tj0 + r % NCC;
        const float* base =
            g_qkv + (size_t)(pixbase + gi * WW + gj) * (3 * CC) + CC + head * HD;
        *(float4*)(sK + r * SROW + d4 * 4) = *(const float4*)(base + d4 * 4);
        *(float4*)(sV + r * SROW + d4 * 4) = *(const float4*)(base + CC + d4 * 4);
    }

    const int i  = tile_i + (t >> 5);
    const int j  = tile_j + (t & 31);
    const int pix = pixbase + i * WW + j;
    float4 q4[8];
    {
        const float4* qp = (const float4*)(g_qkv + (size_t)pix * (3 * CC) + head * HD);
        #pragma unroll
        for (int d4 = 0; d4 < 8; d4++) {
            float4 v = qp[d4];
            v.x *= tn; v.y *= tn; v.z *= tn; v.w *= tn;
            q4[d4] = v;
        }
    }
    __syncthreads();

    const int si = min(max(i - 3, 0), HH - KW);
    const int sj = min(max(j - 3, 0), WW - KW);
    const int lr0 = si - ti0, lc0 = sj - tj0;
    const int ri0 = si - i + 6, rj0 = sj - j + 6;

    float s[49];
    #pragma unroll
    for (int a = 0; a < 7; a++)
        #pragma unroll
        for (int c = 0; c < 7; c++)
            s[a * 7 + c] = srpb[(ri0 + a) * RR + rj0 + c];

    #pragma unroll
    for (int a = 0; a < 7; a++) {
        const float4* kb = (const float4*)(sK + ((lr0 + a) * NCC + lc0) * SROW);
        #pragma unroll
        for (int c = 0; c < 7; c++) {
            const float4* kr = kb + c * (SROW / 4);
            float acc = s[a * 7 + c];
            #pragma unroll
            for (int d4 = 0; d4 < 8; d4++) {
                const float4 kv = kr[d4];
                acc += q4[d4].x * kv.x + q4[d4].y * kv.y
                     + q4[d4].z * kv.z + q4[d4].w * kv.w;
            }
            s[a * 7 + c] = acc;
        }
    }

    float mx = s[0];
    #pragma unroll
    for (int n = 1; n < 49; n++) mx = fmaxf(mx, s[n]);
    float l = 0.f;
    #pragma unroll
    for (int n = 0; n < 49; n++) { s[n] = __expf(s[n] - mx); l += s[n]; }
    const float inv = 1.f / l;

    float4 o4[8];
    #pragma unroll
    for (int d4 = 0; d4 < 8; d4++) o4[d4] = make_float4(0.f, 0.f, 0.f, 0.f);
    #pragma unroll
    for (int a = 0; a < 7; a++) {
        const float4* vb = (const float4*)(sV + ((lr0 + a) * NCC + lc0) * SROW);
        #pragma unroll
        for (int c = 0; c < 7; c++) {
            const float4* vr = vb + c * (SROW / 4);
            const float w = s[a * 7 + c];
            #pragma unroll
            for (int d4 = 0; d4 < 8; d4++) {
                const float4 vv = vr[d4];
                o4[d4].x += w * vv.x; o4[d4].y += w * vv.y;
                o4[d4].z += w * vv.z; o4[d4].w += w * vv.w;
            }
        }
    }

    // write tf32-rounded (feeds proj GEMM with no conversion there)
    float4* op = (float4*)(g_att + (size_t)pix * CC + head * HD);
    #pragma unroll
    for (int d4 = 0; d4 < 8; d4++) {
        float4 o;
        o.x = __uint_as_float(f2tf32(o4[d4].x * inv));
        o.y = __uint_as_float(f2tf32(o4[d4].y * inv));
        o.z = __uint_as_float(f2tf32(o4[d4].z * inv));
        o.w = __uint_as_float(f2tf32(o4[d4].w * inv));
        op[d4] = o;
    }
}

// ---------------------------------------------------------------------------
extern "C" void kernel_launch(void* const* d_in, const int* in_sizes, int n_in,
                              void* d_out, int out_size)
{
    const float* x      = (const float*)d_in[0];
    const float* w_qkv  = (const float*)d_in[1];
    const float* rpb    = (const float*)d_in[2];
    const float* temp   = (const float*)d_in[3];
    const float* w_proj = (const float*)d_in[4];
    float* out = (float*)d_out;

    void *qkvp, *attp, *xrp, *wqp, *wpp;
    cudaGetSymbolAddress(&qkvp, g_qkv);
    cudaGetSymbolAddress(&attp, g_att);
    cudaGetSymbolAddress(&xrp,  g_xr);
    cudaGetSymbolAddress(&wqp,  g_wqr);
    cudaGetSymbolAddress(&wpp,  g_wpr);

    cudaFuncSetAttribute(natten2, cudaFuncAttributeMaxDynamicSharedMemorySize,
                         SM_FLOATS * 4);

    // 0) tf32 rounding pre-pass
    round_pass<<<(N4TOT + 255) / 256, 256>>>(x, w_qkv, w_proj);

    // 1) QKV projection: [8192,192] x [576,192]^T -> g_qkv (q pre-scaled)
    gemm_mma<<<dim3(9, NPIX / GBM), 256>>>((const float*)xrp, (const float*)wqp,
                                           (float*)qkvp, 3 * CC, 1);

    // 2) tiled neighborhood attention -> g_att (tf32-rounded)
    natten2<<<dim3(32, BBATCH, NH), 128, SM_FLOATS * 4>>>(rpb, temp);

    // 3) output projection: [8192,192] x [192,192]^T -> out
    gemm_mma<<<dim3(3, NPIX / GBM), 256>>>((const float*)attp, (const float*)wpp,
                                           out, CC, 0);
}

// round 7
// speedup vs baseline: 3.0409x; 1.1116x over previous
#include <cuda_runtime.h>
#include <cuda_fp16.h>
#include <cstdint>

#define BBATCH 2
#define HH 64
#define WW 64
#define CC 192
#define NH 6
#define HD 32
#define KW 7
#define RR 13
#define NPIX (BBATCH*HH*WW)

// scratch (device globals: allocation-free)
__device__ float g_qkv[(size_t)NPIX * 3 * CC];   // qkv activations (fp32, q pre-scaled)
__device__ float g_att[(size_t)NPIX * CC];       // attention output (tf32-rounded)
__device__ float g_xr [(size_t)NPIX * CC];       // x, tf32-rounded
__device__ float g_wqr[(size_t)3 * CC * CC];     // w_qkv, tf32-rounded
__device__ float g_wpr[(size_t)CC * CC];         // w_proj, tf32-rounded

__device__ __forceinline__ uint32_t f2tf32(float x) {
    uint32_t r;
    asm("cvt.rna.tf32.f32 %0, %1;" : "=r"(r) : "f"(x));
    return r;
}

__device__ __forceinline__ uint32_t smem_u32(const void* p) {
    uint32_t a;
    asm("{ .reg .u64 t; cvta.to.shared.u64 t, %1; cvt.u32.u64 %0, t; }"
        : "=r"(a) : "l"(p));
    return a;
}

__device__ __forceinline__ void cp16(uint32_t dst, const void* src) {
    asm volatile("cp.async.cg.shared.global [%0], [%1], 16;"
                 :: "r"(dst), "l"(src));
}
#define CP_COMMIT() asm volatile("cp.async.commit_group;" ::: "memory")
#define CP_WAIT(N)  asm volatile("cp.async.wait_group %0;" :: "n"(N) : "memory")

__device__ __forceinline__ void mma_tf32(float c[4], const uint32_t a[4],
                                         const uint32_t b[2]) {
    asm volatile(
        "mma.sync.aligned.m16n8k8.row.col.f32.tf32.tf32.f32 "
        "{%0,%1,%2,%3}, {%4,%5,%6,%7}, {%8,%9}, {%0,%1,%2,%3};"
        : "+f"(c[0]), "+f"(c[1]), "+f"(c[2]), "+f"(c[3])
        : "r"(a[0]), "r"(a[1]), "r"(a[2]), "r"(a[3]), "r"(b[0]), "r"(b[1]));
}

// ---------------------------------------------------------------------------
// Pre-pass: round three fp32 arrays to tf32-representable fp32.
// ---------------------------------------------------------------------------
#define N4X ((NPIX * CC) / 4)
#define N4Q ((3 * CC * CC) / 4)
#define N4P ((CC * CC) / 4)
#define N4TOT (N4X + N4Q + N4P)

__global__ __launch_bounds__(256)
void round_pass(const float* __restrict__ x, const float* __restrict__ wq,
                const float* __restrict__ wp)
{
    const int idx = blockIdx.x * 256 + threadIdx.x;
    if (idx >= N4TOT) return;
    const float4* src;
    float4* dst;
    int off;
    if (idx < N4X)            { src = (const float4*)x;  dst = (float4*)g_xr;  off = idx; }
    else if (idx < N4X + N4Q) { src = (const float4*)wq; dst = (float4*)g_wqr; off = idx - N4X; }
    else                      { src = (const float4*)wp; dst = (float4*)g_wpr; off = idx - N4X - N4Q; }
    const float4 v = src[off];
    float4 o;
    o.x = __uint_as_float(f2tf32(v.x));
    o.y = __uint_as_float(f2tf32(v.y));
    o.z = __uint_as_float(f2tf32(v.z));
    o.w = __uint_as_float(f2tf32(v.w));
    dst[off] = o;
}

// ---------------------------------------------------------------------------
// Tensor-core GEMM via mma.sync tf32, cp.async double-buffered.
// Template BM = 128 (QKV, 3 CTAs/SM) or 64 (proj, 4 CTAs/SM, denser grid).
// 256 threads = 8 warps; warp grid (BM/32) x WN; warp tile 32 x (64/WN).
// ---------------------------------------------------------------------------
#define GBK 32
#define GKD 192
#define NCHUNK (GKD / GBK)

template<int BM>
__global__ void __launch_bounds__(256, BM == 128 ? 3 : 4)
gemm_mma(const float* __restrict__ A, const float* __restrict__ W,
         float* __restrict__ C, int Ncols, int scaleQ)
{
    constexpr int WN = (BM == 128) ? 2 : 4;   // N-direction warps
    constexpr int NT = 8 / WN;                // n mma-tiles (of 8) per warp
    constexpr int AU = BM / 32;               // A 16B-units per thread

    __shared__ uint32_t As[2][BM][GBK];
    __shared__ uint32_t Bs[2][64][GBK];

    const int t    = threadIdx.x;
    const int wid  = t >> 5, lane = t & 31;
    const int g    = lane >> 2, q4 = lane & 3;
    const int wM   = wid / WN, wN = wid % WN;
    const int bm   = blockIdx.y * BM;
    const int bn   = blockIdx.x * 64;

    uint32_t a_dst[2][AU], b_dst[2][2];
    const float* a_src[AU];
    const float* b_src[2];
    #pragma unroll
    for (int i = 0; i < AU; i++) {
        const int u = t + i * 256, r = u >> 3, c = u & 7;
        a_src[i] = A + (size_t)(bm + r) * GKD + c * 4;
        #pragma unroll
        for (int bf = 0; bf < 2; bf++)
            a_dst[bf][i] = smem_u32(&As[bf][r][(c ^ (r & 7)) * 4]);
    }
    #pragma unroll
    for (int i = 0; i < 2; i++) {
        const int u = t + i * 256, r = u >> 3, c = u & 7;
        b_src[i] = W + (size_t)(bn + r) * GKD + c * 4;
        #pragma unroll
        for (int bf = 0; bf < 2; bf++)
            b_dst[bf][i] = smem_u32(&Bs[bf][r][(c ^ (r & 7)) * 4]);
    }

    #pragma unroll
    for (int i = 0; i < AU; i++) cp16(a_dst[0][i], a_src[i]);
    #pragma unroll
    for (int i = 0; i < 2; i++) cp16(b_dst[0][i], b_src[i]);
    CP_COMMIT();

    float acc[2][NT][4] = {};

    #pragma unroll
    for (int kc = 0; kc < NCHUNK; kc++) {
        const int buf = kc & 1;
        if (kc + 1 < NCHUNK) {
            const int ko = (kc + 1) * GBK;
            const int nb = (kc + 1) & 1;
            #pragma unroll
            for (int i = 0; i < AU; i++) cp16(a_dst[nb][i], a_src[i] + ko);
            #pragma unroll
            for (int i = 0; i < 2; i++) cp16(b_dst[nb][i], b_src[i] + ko);
            CP_COMMIT();
            CP_WAIT(1);
        } else {
            CP_WAIT(0);
        }
        __syncthreads();

        #pragma unroll
        for (int k8 = 0; k8 < GBK / 8; k8++) {
            const int w0 = ((k8 * 2) ^ g) * 4 + q4;
            const int w1 = ((k8 * 2 + 1) ^ g) * 4 + q4;
            uint32_t a[2][4], b[NT][2];
            #pragma unroll
            for (int mt = 0; mt < 2; mt++) {
                const int r = wM * 32 + mt * 16 + g;
                a[mt][0] = As[buf][r][w0];
                a[mt][1] = As[buf][r + 8][w0];
                a[mt][2] = As[buf][r][w1];
                a[mt][3] = As[buf][r + 8][w1];
            }
            #pragma unroll
            for (int nt = 0; nt < NT; nt++) {
                const int r = wN * (8 * NT) + nt * 8 + g;
                b[nt][0] = Bs[buf][r][w0];
                b[nt][1] = Bs[buf][r][w1];
            }
            #pragma unroll
            for (int mt = 0; mt < 2; mt++)
                #pragma unroll
                for (int nt = 0; nt < NT; nt++)
                    mma_tf32(acc[mt][nt], a[mt], b[nt]);
        }
        __syncthreads();
    }

    const float sc = (scaleQ && bn < CC) ? 0.17677669529663687f : 1.0f;
    #pragma unroll
    for (int mt = 0; mt < 2; mt++) {
        const int row0 = bm + wM * 32 + mt * 16 + g;
        #pragma unroll
        for (int nt = 0; nt < NT; nt++) {
            const int col = bn + wN * (8 * NT) + nt * 8 + q4 * 2;
            float2 lo = make_float2(acc[mt][nt][0] * sc, acc[mt][nt][1] * sc);
            float2 hi = make_float2(acc[mt][nt][2] * sc, acc[mt][nt][3] * sc);
            *(float2*)(C + (size_t)row0 * Ncols + col) = lo;
            *(float2*)(C + (size_t)(row0 + 8) * Ncols + col) = hi;
        }
    }
}

// ---------------------------------------------------------------------------
// Tiled neighborhood attention, fp16 K/V in smem.
// Block: 4x32 pixel tile, one head, one batch; 128 threads = 1 thread/pixel.
// K,V rows: 32 halfs, stride 40 halfs (80B = 20 words): uint4 reads are
// bank-conflict-free (20r mod 32 distinct over 8 consecutive lanes).
// QK: HFMA2 on half2 (scores tiny -> abs fp16 error ~1e-4, harmless).
// AV: fp16 load, cvt->fp32 FFMA accumulate (keeps output error ~2e-4).
// ---------------------------------------------------------------------------
#define TILE_H 4
#define TILE_W 32
#define NRR (TILE_H + KW - 1)     // 10
#define NCC (TILE_W + KW - 1)     // 38
#define NNEI (NRR * NCC)          // 380
#define SROWH 40                  // halfs per row (80B)
#define SM_BYTES (2 * NNEI * SROWH * 2 + RR * RR * 4)

__global__ __launch_bounds__(128)
void natten2(const float* __restrict__ rpb, const float* __restrict__ temp)
{
    extern __shared__ char smraw[];
    __half* sKh  = (__half*)smraw;
    __half* sVh  = sKh + NNEI * SROWH;
    float*  srpb = (float*)(sVh + NNEI * SROWH);

    const int t      = threadIdx.x;
    const int tile   = blockIdx.x;
    const int bI     = blockIdx.y;
    const int head   = blockIdx.z;
    const int tile_i = (tile >> 1) * TILE_H;
    const int tile_j = (tile & 1) * TILE_W;
    const int ti0 = min(max(tile_i - 3, 0), HH - NRR);
    const int tj0 = min(max(tile_j - 3, 0), WW - NCC);
    const int pixbase = bI * HH * WW;

    const float tn = temp[head];
    for (int idx = t; idx < RR * RR; idx += 128)
        srpb[idx] = rpb[head * RR * RR + idx] * tn;

    // stage K,V as fp16
    for (int idx = t; idx < NNEI * 8; idx += 128) {
        const int d4 = idx & 7, r = idx >> 3;
        const int gi = ti0 + r / NCC, gj = tj0 + r % NCC;
        const float* base =
            g_qkv + (size_t)(pixbase + gi * WW + gj) * (3 * CC) + CC + head * HD;
        const float4 kk = *(const float4*)(base + d4 * 4);
        const float4 vv = *(const float4*)(base + CC + d4 * 4);
        __half* kp = sKh + r * SROWH + d4 * 4;
        __half* vp = sVh + r * SROWH + d4 * 4;
        *(__half2*)(kp)     = __floats2half2_rn(kk.x, kk.y);
        *(__half2*)(kp + 2) = __floats2half2_rn(kk.z, kk.w);
        *(__half2*)(vp)     = __floats2half2_rn(vv.x, vv.y);
        *(__half2*)(vp + 2) = __floats2half2_rn(vv.z, vv.w);
    }

    // q (fp32 gmem, already qs-scaled) -> half2 regs with temperature applied
    const int i  = tile_i + (t >> 5);
    const int j  = tile_j + (t & 31);
    const int pix = pixbase + i * WW + j;
    __half2 qh[16];
    {
        const float4* qp = (const float4*)(g_qkv + (size_t)pix * (3 * CC) + head * HD);
        #pragma unroll
        for (int d4 = 0; d4 < 8; d4++) {
            const float4 v = qp[d4];
            qh[d4 * 2]     = __floats2half2_rn(v.x * tn, v.y * tn);
            qh[d4 * 2 + 1] = __floats2half2_rn(v.z * tn, v.w * tn);
        }
    }
    __syncthreads();

    const int si = min(max(i - 3, 0), HH - KW);
    const int sj = min(max(j - 3, 0), WW - KW);
    const int lr0 = si - ti0, lc0 = sj - tj0;
    const int ri0 = si - i + 6, rj0 = sj - j + 6;

    float s[49];
    #pragma unroll
    for (int a = 0; a < 7; a++)
        #pragma unroll
        for (int c = 0; c < 7; c++)
            s[a * 7 + c] = srpb[(ri0 + a) * RR + rj0 + c];

    // QK: HFMA2 over half2, final pair-sum in fp32
    #pragma unroll
    for (int a = 0; a < 7; a++) {
        const __half* kb = sKh + ((lr0 + a) * NCC + lc0) * SROWH;
        #pragma unroll
        for (int c = 0; c < 7; c++) {
            const uint4* kr = (const uint4*)(kb + c * SROWH);
            __half2 acc = __float2half2_rn(0.f);
            #pragma unroll
            for (int ch = 0; ch < 4; ch++) {
                const uint4 kv = kr[ch];
                acc = __hfma2(qh[ch * 4 + 0], *(const __half2*)&kv.x, acc);
                acc = __hfma2(qh[ch * 4 + 1], *(const __half2*)&kv.y, acc);
                acc = __hfma2(qh[ch * 4 + 2], *(const __half2*)&kv.z, acc);
                acc = __hfma2(qh[ch * 4 + 3], *(const __half2*)&kv.w, acc);
            }
            const float2 f = __half22float2(acc);
            s[a * 7 + c] += f.x + f.y;
        }
    }

    float mx = s[0];
    #pragma unroll
    for (int n = 1; n < 49; n++) mx = fmaxf(mx, s[n]);
    float l = 0.f;
    #pragma unroll
    for (int n = 0; n < 49; n++) { s[n] = __expf(s[n] - mx); l += s[n]; }
    const float inv = 1.f / l;

    // AV: fp16 loads, fp32 accumulate
    float o[32];
    #pragma unroll
    for (int d = 0; d < 32; d++) o[d] = 0.f;
    #pragma unroll
    for (int a = 0; a < 7; a++) {
        const __half* vb = sVh + ((lr0 + a) * NCC + lc0) * SROWH;
        #pragma unroll
        for (int c = 0; c < 7; c++) {
            const uint4* vr = (const uint4*)(vb + c * SROWH);
            const float w = s[a * 7 + c];
            #pragma unroll
            for (int ch = 0; ch < 4; ch++) {
                const uint4 vv = vr[ch];
                const float2 p0 = __half22float2(*(const __half2*)&vv.x);
                const float2 p1 = __half22float2(*(const __half2*)&vv.y);
                const float2 p2 = __half22float2(*(const __half2*)&vv.z);
                const float2 p3 = __half22float2(*(const __half2*)&vv.w);
                o[ch * 8 + 0] += w * p0.x; o[ch * 8 + 1] += w * p0.y;
                o[ch * 8 + 2] += w * p1.x; o[ch * 8 + 3] += w * p1.y;
                o[ch * 8 + 4] += w * p2.x; o[ch * 8 + 5] += w * p2.y;
                o[ch * 8 + 6] += w * p3.x; o[ch * 8 + 7] += w * p3.y;
            }
        }
    }

    // write tf32-rounded (feeds proj GEMM)
    float4* op = (float4*)(g_att + (size_t)pix * CC + head * HD);
    #pragma unroll
    for (int d4 = 0; d4 < 8; d4++) {
        float4 ov;
        ov.x = __uint_as_float(f2tf32(o[d4 * 4 + 0] * inv));
        ov.y = __uint_as_float(f2tf32(o[d4 * 4 + 1] * inv));
        ov.z = __uint_as_float(f2tf32(o[d4 * 4 + 2] * inv));
        ov.w = __uint_as_float(f2tf32(o[d4 * 4 + 3] * inv));
        op[d4] = ov;
    }
}

// ---------------------------------------------------------------------------
extern "C" void kernel_launch(void* const* d_in, const int* in_sizes, int n_in,
                              void* d_out, int out_size)
{
    const float* x      = (const float*)d_in[0];
    const float* w_qkv  = (const float*)d_in[1];
    const float* rpb    = (const float*)d_in[2];
    const float* temp   = (const float*)d_in[3];
    const float* w_proj = (const float*)d_in[4];
    float* out = (float*)d_out;

    void *qkvp, *attp, *xrp, *wqp, *wpp;
    cudaGetSymbolAddress(&qkvp, g_qkv);
    cudaGetSymbolAddress(&attp, g_att);
    cudaGetSymbolAddress(&xrp,  g_xr);
    cudaGetSymbolAddress(&wqp,  g_wqr);
    cudaGetSymbolAddress(&wpp,  g_wpr);

    cudaFuncSetAttribute(natten2, cudaFuncAttributeMaxDynamicSharedMemorySize,
                         SM_BYTES);

    // 0) tf32 rounding pre-pass
    round_pass<<<(N4TOT + 255) / 256, 256>>>(x, w_qkv, w_proj);

    // 1) QKV projection: [8192,192] x [576,192]^T -> g_qkv (q pre-scaled)
    gemm_mma<128><<<dim3(9, NPIX / 128), 256>>>((const float*)xrp,
                                                (const float*)wqp,
                                                (float*)qkvp, 3 * CC, 1);

    // 2) tiled neighborhood attention -> g_att (tf32-rounded)
    natten2<<<dim3(32, BBATCH, NH), 128, SM_BYTES>>>(rpb, temp);

    // 3) output projection: [8192,192] x [192,192]^T -> out
    gemm_mma<64><<<dim3(3, NPIX / 64), 256>>>((const float*)attp,
                                              (const float*)wpp,
                                              out, CC, 0);
}